// round 11
// baseline (speedup 1.0000x reference)
#include <cuda_runtime.h>
#include <cuda_bf16.h>
#include <cfloat>
#include <math.h>

// Problem constants
#define BS    16
#define CAP   64
#define VOCAB 50265
#define TOPK  5
#define SEQ   256
#define AT    32
#define D     768
#define END_ID 2

#define QPAD  772      // padded q-row stride in floats
#define NCHUNK 12      // 12 * 1024 float4s in chunked region
#define CANDCAP 512    // candidate buffer capacity

// Scratch (device globals — no allocation allowed)
__device__ float g_sce[BS * CAP * D];   // [16,64,768]
__device__ float g_att[BS * AT * D];    // [16,32,768]

__device__ __forceinline__ float max4(const float4& x) {
    return fmaxf(fmaxf(x.x, x.y), fmaxf(x.z, x.w));
}

// ---------------------------------------------------------------------------
// Kernel 1: per (b,c) row — top-5 over vocab, softmax, weighted embed gather.
// Grid: 1024 blocks, 256 threads. (Round-8 best config: regs 32, occ ~79%.)
// ---------------------------------------------------------------------------
__global__ __launch_bounds__(256) void topk_sce_kernel(
    const float* __restrict__ caption_out,   // [16,64,VOCAB]
    const float* __restrict__ embed_table)   // [VOCAB, D]
{
    const int row = blockIdx.x;              // 0..1023  (= b*CAP + c)
    const int t   = threadIdx.x;
    const float* rowp = caption_out + (size_t)row * VOCAB;

    __shared__ float schunk[NCHUNK * 256];   // per-chunk maxes (12 KB)
    __shared__ float bv[CANDCAP];
    __shared__ int   bi[CANDCAP];
    __shared__ int   scnt;
    __shared__ float wmax[8];
    __shared__ float sTh;
    __shared__ float fv[TOPK];
    __shared__ int   fi[TOPK];

    if (t == 0) scnt = 0;

    // alignment prologue
    const int mis = (int)(((size_t)rowp >> 2) & 3);
    const int pre = (4 - mis) & 3;                    // scalar prefix (0..3)
    const int n4  = (VOCAB - pre) >> 2;               // aligned float4 count
    const int tail_start = pre + (n4 << 2);
    const int ntail = VOCAB - tail_start;             // 0..3
    const float4* base4 = (const float4*)(rowp + pre);

    // ================= Pass A: branchless max scan =================
    float m0 = -FLT_MAX, m1 = -FLT_MAX;
    #pragma unroll 2
    for (int i = 0; i < NCHUNK; i++) {
        const int e = t + (i << 10);
        float4 x0 = base4[e];
        float4 x1 = base4[e + 256];
        float4 x2 = base4[e + 512];
        float4 x3 = base4[e + 768];
        float cm = fmaxf(fmaxf(max4(x0), max4(x1)), fmaxf(max4(x2), max4(x3)));
        schunk[(i << 8) + t] = cm;
        m0 = fmaxf(m0, cm);
    }
    for (int e = (NCHUNK << 10) + t; e < n4; e += 256)
        m1 = fmaxf(m1, max4(base4[e]));
    if (t < pre) m1 = fmaxf(m1, rowp[t]);
    if (t >= 32 && t < 32 + ntail) m1 = fmaxf(m1, rowp[tail_start + (t - 32)]);

    float runMax = fmaxf(m0, m1);
    #pragma unroll
    for (int off = 16; off > 0; off >>= 1)
        runMax = fmaxf(runMax, __shfl_xor_sync(0xffffffffu, runMax, off));
    const int lane = t & 31;
    const int wid  = t >> 5;
    if (lane == 0) wmax[wid] = runMax;
    __syncthreads();

    // T = 5th largest of the 8 warp maxes (>=5 distinct elements >= T exist)
    if (t == 0) {
        float a0=wmax[0],a1=wmax[1],a2=wmax[2],a3=wmax[3],
              a4=wmax[4],a5=wmax[5],a6=wmax[6],a7=wmax[7];
        float T = 0.0f;
        #pragma unroll
        for (int r = 0; r < 5; r++) {
            float mx = fmaxf(fmaxf(fmaxf(a0,a1),fmaxf(a2,a3)),
                             fmaxf(fmaxf(a4,a5),fmaxf(a6,a7)));
            T = mx;
            if      (a0==mx) a0=-FLT_MAX; else if (a1==mx) a1=-FLT_MAX;
            else if (a2==mx) a2=-FLT_MAX; else if (a3==mx) a3=-FLT_MAX;
            else if (a4==mx) a4=-FLT_MAX; else if (a5==mx) a5=-FLT_MAX;
            else if (a6==mx) a6=-FLT_MAX; else a7=-FLT_MAX;
        }
        sTh = T;
    }
    __syncthreads();
    const float T = sTh;

    // ================= Pass B: sparse candidate collection =================
    #pragma unroll
    for (int i = 0; i < NCHUNK; i++) {
        if (schunk[(i << 8) + t] >= T) {         // rare: ~17 chunks per block
            const int e = t + (i << 10);
            #pragma unroll
            for (int s = 0; s < 4; s++) {
                const int ee = e + s * 256;
                float4 x = base4[ee];
                const int gb = pre + 4 * ee;
                float xv[4] = {x.x, x.y, x.z, x.w};
                #pragma unroll
                for (int c = 0; c < 4; c++) {
                    if (xv[c] >= T) {
                        int slot = atomicAdd(&scnt, 1);
                        if (slot < CANDCAP) { bv[slot] = xv[c]; bi[slot] = gb + c; }
                    }
                }
            }
        }
    }
    for (int e = (NCHUNK << 10) + t; e < n4; e += 256) {
        float4 x = base4[e];
        if (max4(x) >= T) {
            const int gb = pre + 4 * e;
            float xv[4] = {x.x, x.y, x.z, x.w};
            #pragma unroll
            for (int c = 0; c < 4; c++) {
                if (xv[c] >= T) {
                    int slot = atomicAdd(&scnt, 1);
                    if (slot < CANDCAP) { bv[slot] = xv[c]; bi[slot] = gb + c; }
                }
            }
        }
    }
    if (t < pre) {
        float x = rowp[t];
        if (x >= T) {
            int slot = atomicAdd(&scnt, 1);
            if (slot < CANDCAP) { bv[slot] = x; bi[slot] = t; }
        }
    }
    if (t >= 32 && t < 32 + ntail) {
        int e = tail_start + (t - 32);
        float x = rowp[e];
        if (x >= T) {
            int slot = atomicAdd(&scnt, 1);
            if (slot < CANDCAP) { bv[slot] = x; bi[slot] = e; }
        }
    }
    __syncthreads();

    const int n = (scnt < CANDCAP) ? scnt : CANDCAP;   // guaranteed >= 5

    // ================= 5 rounds of block argmax over candidates =============
    __shared__ float wmv[8];
    __shared__ int   wmp[8];
    for (int r = 0; r < TOPK; r++) {
        float bm = -FLT_MAX; int bp = 0;
        #pragma unroll
        for (int s = 0; s < CANDCAP; s += 256) {
            int idx = t + s;
            float v = (idx < n) ? bv[idx] : -FLT_MAX;
            if (v > bm) { bm = v; bp = idx; }
        }
        #pragma unroll
        for (int off = 16; off > 0; off >>= 1) {
            float ov = __shfl_down_sync(0xffffffffu, bm, off);
            int   op = __shfl_down_sync(0xffffffffu, bp, off);
            if (ov > bm) { bm = ov; bp = op; }
        }
        if (lane == 0) { wmv[wid] = bm; wmp[wid] = bp; }
        __syncthreads();
        if (t == 0) {
            float gm = wmv[0]; int gp = wmp[0];
            #pragma unroll
            for (int w = 1; w < 8; w++)
                if (wmv[w] > gm) { gm = wmv[w]; gp = wmp[w]; }
            fv[r] = gm;
            fi[r] = bi[gp];
            bv[gp] = -FLT_MAX;
        }
        __syncthreads();
    }

    // ---- softmax over 5 + weighted embed gather ----
    float mx = fv[0];
    float p0 = __expf(fv[0]-mx), p1 = __expf(fv[1]-mx), p2 = __expf(fv[2]-mx),
          p3 = __expf(fv[3]-mx), p4 = __expf(fv[4]-mx);
    float inv = 1.0f / (p0+p1+p2+p3+p4);
    p0*=inv; p1*=inv; p2*=inv; p3*=inv; p4*=inv;

    const float* e0 = embed_table + (size_t)fi[0]*D;
    const float* e1 = embed_table + (size_t)fi[1]*D;
    const float* e2 = embed_table + (size_t)fi[2]*D;
    const float* e3 = embed_table + (size_t)fi[3]*D;
    const float* e4 = embed_table + (size_t)fi[4]*D;

    float* sce = g_sce + (size_t)row * D;
    #pragma unroll
    for (int j = 0; j < 3; j++) {
        int d = t + j*256;
        sce[d] = p0*e0[d] + p1*e1[d] + p2*e2[d] + p3*e3[d] + p4*e4[d];
    }
}

// ---------------------------------------------------------------------------
// Kernel 2: attention. Block = (b, query-group of 4). Grid 128, 512 threads.
// 16 warps: warp-per-key scoring (4 passes), 1/sqrt(D) folded into staged q.
// ---------------------------------------------------------------------------
__global__ __launch_bounds__(512) void attn_kernel(
    const float* __restrict__ q_in,          // [16,32,768]
    const int*   __restrict__ caption_len)   // [16]
{
    const int b  = blockIdx.x >> 3;
    const int qg = blockIdx.x & 7;           // queries qg*4 .. qg*4+3
    const int t  = threadIdx.x;
    const int wid  = t >> 5;                 // 0..15
    const int lane = t & 31;

    const float* sce = g_sce + (size_t)b * CAP * D;
    const float scale = 1.0f / sqrtf((float)D);

    __shared__ float sq[4 * QPAD];
    __shared__ float ssc[4][CAP];

    // stage the 4 query rows, pre-scaled by 1/sqrt(D)
    {
        const float4* qg4 = (const float4*)(q_in + ((size_t)b * AT + qg*4) * D);
        for (int i = t; i < 4 * (D/4); i += 512) {
            int qi = i / (D/4), j = i % (D/4);
            float4 v = qg4[qi * (D/4) + j];
            v.x *= scale; v.y *= scale; v.z *= scale; v.w *= scale;
            *(float4*)&sq[qi * QPAD + j * 4] = v;
        }
    }
    __syncthreads();

    // scores: warp w handles keys w, w+16, w+32, w+48
    #pragma unroll
    for (int kb = 0; kb < 4; kb++) {
        const int k = kb * 16 + wid;
        const float4* krow = (const float4*)(sce + (size_t)k * D);
        float a0 = 0.f, a1 = 0.f, a2 = 0.f, a3 = 0.f;
        #pragma unroll
        for (int i = 0; i < 6; i++) {
            const int j = lane + 32 * i;       // float4 index, 0..191
            float4 kk = krow[j];
            float4 q0 = *(const float4*)&sq[0*QPAD + j*4];
            float4 q1 = *(const float4*)&sq[1*QPAD + j*4];
            float4 q2 = *(const float4*)&sq[2*QPAD + j*4];
            float4 q3 = *(const float4*)&sq[3*QPAD + j*4];
            a0 = fmaf(kk.x,q0.x, fmaf(kk.y,q0.y, fmaf(kk.z,q0.z, fmaf(kk.w,q0.w, a0))));
            a1 = fmaf(kk.x,q1.x, fmaf(kk.y,q1.y, fmaf(kk.z,q1.z, fmaf(kk.w,q1.w, a1))));
            a2 = fmaf(kk.x,q2.x, fmaf(kk.y,q2.y, fmaf(kk.z,q2.z, fmaf(kk.w,q2.w, a2))));
            a3 = fmaf(kk.x,q3.x, fmaf(kk.y,q3.y, fmaf(kk.z,q3.z, fmaf(kk.w,q3.w, a3))));
        }
        #pragma unroll
        for (int off = 16; off > 0; off >>= 1) {
            a0 += __shfl_xor_sync(0xffffffffu, a0, off);
            a1 += __shfl_xor_sync(0xffffffffu, a1, off);
            a2 += __shfl_xor_sync(0xffffffffu, a2, off);
            a3 += __shfl_xor_sync(0xffffffffu, a3, off);
        }
        if (lane == 0) {
            ssc[0][k] = a0; ssc[1][k] = a1; ssc[2][k] = a2; ssc[3][k] = a3;
        }
    }
    __syncthreads();

    // softmax per query row; warps 0-3 handle rows 0-3 (scores pre-scaled)
    const int clen = caption_len[b];
    if (wid < 4) {
        float s0 = (lane      < clen) ? ssc[wid][lane]      : -1e9f;
        float s1 = (lane + 32 < clen) ? ssc[wid][lane + 32] : -1e9f;
        float mx = fmaxf(s0, s1);
        #pragma unroll
        for (int off = 16; off > 0; off >>= 1)
            mx = fmaxf(mx, __shfl_xor_sync(0xffffffffu, mx, off));
        float e0 = __expf(s0 - mx), e1 = __expf(s1 - mx);
        float sum = e0 + e1;
        #pragma unroll
        for (int off = 16; off > 0; off >>= 1)
            sum += __shfl_xor_sync(0xffffffffu, sum, off);
        float isum = 1.0f / sum;
        ssc[wid][lane]      = e0 * isum;
        ssc[wid][lane + 32] = e1 * isum;
    }
    __syncthreads();

    // output: threads 0..383 own dims t and t+384 for all 4 queries
    if (t < 384) {
        float acc[4][2];
        #pragma unroll
        for (int qi = 0; qi < 4; qi++) { acc[qi][0]=0; acc[qi][1]=0; }

        #pragma unroll 4
        for (int k = 0; k < CAP; k++) {
            const float* srow = sce + (size_t)k * D;
            float a0 = srow[t], a1 = srow[t + 384];
            #pragma unroll
            for (int qi = 0; qi < 4; qi++) {
                float aw = ssc[qi][k];
                acc[qi][0] = fmaf(aw, a0, acc[qi][0]);
                acc[qi][1] = fmaf(aw, a1, acc[qi][1]);
            }
        }
        #pragma unroll
        for (int qi = 0; qi < 4; qi++) {
            float* orow = g_att + ((size_t)b * AT + qg*4 + qi) * D;
            orow[t]       = acc[qi][0];
            orow[t + 384] = acc[qi][1];
        }
    }
}

// ---------------------------------------------------------------------------
// Kernel 3: final assembly. Block per (b,s). Grid 4096, 192 threads (float4).
// ---------------------------------------------------------------------------
__global__ __launch_bounds__(192) void assemble_kernel(
    const float* __restrict__ embed_table,
    const int*   __restrict__ input_ids,     // [16,256]
    const int*   __restrict__ origin_len,    // [16]
    const int*   __restrict__ target_len,    // [16]
    float*       __restrict__ out)           // [16,256,768]
{
    const int bs = blockIdx.x;
    const int b  = bs >> 8;
    const int s  = bs & 255;
    const int rel = s - origin_len[b];
    const int tl  = target_len[b];

    const float* src;
    if (rel >= 0 && rel < tl)      src = g_att + ((size_t)b * AT + rel) * D;
    else if (rel == tl)            src = embed_table + (size_t)END_ID * D;
    else                           src = embed_table + (size_t)input_ids[bs] * D;

    ((float4*)(out + (size_t)bs * D))[threadIdx.x] = ((const float4*)src)[threadIdx.x];
}

// ---------------------------------------------------------------------------
extern "C" void kernel_launch(void* const* d_in, const int* in_sizes, int n_in,
                              void* d_out, int out_size)
{
    const float* caption_out      = (const float*)d_in[0];   // [16,64,50265]
    const float* embed_table      = (const float*)d_in[1];   // [50265,768]
    const float* inputs_embeds_at = (const float*)d_in[2];   // [16,32,768]
    const int*   input_ids        = (const int*)  d_in[3];   // [16,256]
    const int*   origin_len       = (const int*)  d_in[4];   // [16]
    const int*   target_len       = (const int*)  d_in[5];   // [16]
    const int*   caption_len      = (const int*)  d_in[6];   // [16]
    float* out = (float*)d_out;

    topk_sce_kernel<<<BS * CAP, 256>>>(caption_out, embed_table);
    attn_kernel<<<BS * 8, 512>>>(inputs_embeds_at, caption_len);
    assemble_kernel<<<BS * SEQ, 192>>>(embed_table, input_ids,
                                       origin_len, target_len, out);
}

// round 13
// speedup vs baseline: 1.1886x; 1.1886x over previous
#include <cuda_runtime.h>
#include <cuda_bf16.h>
#include <cfloat>
#include <math.h>

// Problem constants
#define BS    16
#define CAP   64
#define VOCAB 50265
#define TOPK  5
#define SEQ   256
#define AT    32
#define D     768
#define END_ID 2

#define QPAD  772      // padded q-row stride in floats
#define NSUB  4        // sub-blocks per row
#define SUBLEN 12567   // ceil(VOCAB/4); 4*12567 = 50268 >= 50265
#define NCHUNK 3       // 3 * 1024 float4s chunked per sub-block
#define CANDCAP 256    // candidate buffer capacity (expected ~10 survivors)

// Scratch (device globals — no allocation allowed)
__device__ float g_sce[BS * CAP * D];            // [16,64,768]
__device__ float g_att[BS * AT * D];             // [16,32,768]
__device__ float g_cand_v[BS * CAP * NSUB * TOPK];
__device__ int   g_cand_i[BS * CAP * NSUB * TOPK];

__device__ __forceinline__ float max4(const float4& x) {
    return fmaxf(fmaxf(x.x, x.y), fmaxf(x.z, x.w));
}

// ---------------------------------------------------------------------------
// Kernel 1a: scan. Block = (row, quarter). Grid 4096, 256 threads.
// Local top-5 over ~12.6K elements -> g_cand. Fine granularity so trailing
// waves rebalance (kills the multi-CTA-spread tail seen at grid 1024).
// ---------------------------------------------------------------------------
__global__ __launch_bounds__(256) void scan_kernel(
    const float* __restrict__ caption_out)   // [16,64,VOCAB]
{
    const int row = blockIdx.x >> 2;         // 0..1023
    const int sub = blockIdx.x & 3;          // 0..3
    const int t   = threadIdx.x;
    const int lane = t & 31;
    const int wid  = t >> 5;

    const int s0 = sub * SUBLEN;
    const int s1 = (s0 + SUBLEN < VOCAB) ? (s0 + SUBLEN) : VOCAB;
    const int len = s1 - s0;                 // 12564..12567
    const float* rp = caption_out + (size_t)row * VOCAB + s0;

    __shared__ float schunk[NCHUNK * 256];   // per-chunk maxes (3 KB)
    __shared__ float bv[CANDCAP];
    __shared__ int   bi[CANDCAP];
    __shared__ int   scnt;
    __shared__ float wmax[8];
    __shared__ float sTh;
    __shared__ float fv[TOPK];
    __shared__ int   fi[TOPK];
    __shared__ float wmv[8];
    __shared__ int   wmp[8];

    if (t == 0) scnt = 0;

    // alignment prologue within subrange
    const int mis = (int)(((size_t)rp >> 2) & 3);
    const int pre = (4 - mis) & 3;           // scalar prefix (0..3), pre << len
    const int n4  = (len - pre) >> 2;        // aligned float4 count (>= 3140)
    const int tail_start = pre + (n4 << 2);
    const int ntail = len - tail_start;      // 0..3
    const float4* base4 = (const float4*)(rp + pre);

    // ================= Pass A: branchless max scan =================
    float m0 = -FLT_MAX, m1 = -FLT_MAX;
    #pragma unroll
    for (int i = 0; i < NCHUNK; i++) {
        const int e = t + (i << 10);
        float4 x0 = base4[e];
        float4 x1 = base4[e + 256];
        float4 x2 = base4[e + 512];
        float4 x3 = base4[e + 768];
        float cm = fmaxf(fmaxf(max4(x0), max4(x1)), fmaxf(max4(x2), max4(x3)));
        schunk[(i << 8) + t] = cm;
        m0 = fmaxf(m0, cm);
    }
    for (int e = (NCHUNK << 10) + t; e < n4; e += 256)
        m1 = fmaxf(m1, max4(base4[e]));
    if (t < pre) m1 = fmaxf(m1, rp[t]);
    if (t >= 32 && t < 32 + ntail) m1 = fmaxf(m1, rp[tail_start + (t - 32)]);

    float runMax = fmaxf(m0, m1);
    #pragma unroll
    for (int off = 16; off > 0; off >>= 1)
        runMax = fmaxf(runMax, __shfl_xor_sync(0xffffffffu, runMax, off));
    if (lane == 0) wmax[wid] = runMax;
    __syncthreads();

    // T = 5th largest of the 8 warp maxes (>=5 distinct elements >= T exist)
    if (t == 0) {
        float a0=wmax[0],a1=wmax[1],a2=wmax[2],a3=wmax[3],
              a4=wmax[4],a5=wmax[5],a6=wmax[6],a7=wmax[7];
        float T = 0.0f;
        #pragma unroll
        for (int r = 0; r < 5; r++) {
            float mx = fmaxf(fmaxf(fmaxf(a0,a1),fmaxf(a2,a3)),
                             fmaxf(fmaxf(a4,a5),fmaxf(a6,a7)));
            T = mx;
            if      (a0==mx) a0=-FLT_MAX; else if (a1==mx) a1=-FLT_MAX;
            else if (a2==mx) a2=-FLT_MAX; else if (a3==mx) a3=-FLT_MAX;
            else if (a4==mx) a4=-FLT_MAX; else if (a5==mx) a5=-FLT_MAX;
            else if (a6==mx) a6=-FLT_MAX; else a7=-FLT_MAX;
        }
        sTh = T;
    }
    __syncthreads();
    const float T = sTh;

    // ================= Pass B: sparse candidate collection =================
    for (int i = 0; i < NCHUNK; i++) {
        if (schunk[(i << 8) + t] >= T) {         // rare after threshold
            const int e = t + (i << 10);
            for (int s = 0; s < 4; s++) {
                const int ee = e + s * 256;
                float4 x = base4[ee];
                const int gb = s0 + pre + 4 * ee;
                float xv[4] = {x.x, x.y, x.z, x.w};
                for (int c = 0; c < 4; c++) {
                    if (xv[c] >= T) {
                        int slot = atomicAdd(&scnt, 1);
                        if (slot < CANDCAP) { bv[slot] = xv[c]; bi[slot] = gb + c; }
                    }
                }
            }
        }
    }
    for (int e = (NCHUNK << 10) + t; e < n4; e += 256) {
        float4 x = base4[e];
        if (max4(x) >= T) {
            const int gb = s0 + pre + 4 * e;
            float xv[4] = {x.x, x.y, x.z, x.w};
            for (int c = 0; c < 4; c++) {
                if (xv[c] >= T) {
                    int slot = atomicAdd(&scnt, 1);
                    if (slot < CANDCAP) { bv[slot] = xv[c]; bi[slot] = gb + c; }
                }
            }
        }
    }
    if (t < pre) {
        float x = rp[t];
        if (x >= T) {
            int slot = atomicAdd(&scnt, 1);
            if (slot < CANDCAP) { bv[slot] = x; bi[slot] = s0 + t; }
        }
    }
    if (t >= 32 && t < 32 + ntail) {
        int e = tail_start + (t - 32);
        float x = rp[e];
        if (x >= T) {
            int slot = atomicAdd(&scnt, 1);
            if (slot < CANDCAP) { bv[slot] = x; bi[slot] = s0 + e; }
        }
    }
    __syncthreads();

    const int n = (scnt < CANDCAP) ? scnt : CANDCAP;   // >= 5 by construction

    // ================= 5 rounds of block argmax over candidates =============
    for (int r = 0; r < TOPK; r++) {
        // thread-local scan (CANDCAP=256 -> exactly one slot per thread)
        float bm = (t < n) ? bv[t] : -FLT_MAX;
        int   bp = t;
        #pragma unroll
        for (int off = 16; off > 0; off >>= 1) {
            float ov = __shfl_down_sync(0xffffffffu, bm, off);
            int   op = __shfl_down_sync(0xffffffffu, bp, off);
            if (ov > bm) { bm = ov; bp = op; }
        }
        if (lane == 0) { wmv[wid] = bm; wmp[wid] = bp; }
        __syncthreads();
        if (t == 0) {
            float gm = wmv[0]; int gp = wmp[0];
            #pragma unroll
            for (int w = 1; w < 8; w++)
                if (wmv[w] > gm) { gm = wmv[w]; gp = wmp[w]; }
            fv[r] = gm;
            fi[r] = (gp < CANDCAP) ? bi[gp] : 0;
            if (gp < CANDCAP) bv[gp] = -FLT_MAX;
        }
        __syncthreads();
    }

    if (t < TOPK) {
        g_cand_v[(size_t)blockIdx.x * TOPK + t] = fv[t];
        g_cand_i[(size_t)blockIdx.x * TOPK + t] = fi[t];
    }
}

// ---------------------------------------------------------------------------
// Kernel 1b: per-row reduce of 20 candidates -> top-5, softmax, embed gather.
// Grid 1024 (one per row), 256 threads.
// ---------------------------------------------------------------------------
__global__ __launch_bounds__(256) void sce_kernel(
    const float* __restrict__ embed_table)   // [VOCAB, D]
{
    const int row = blockIdx.x;
    const int t   = threadIdx.x;

    __shared__ float cv[NSUB * TOPK];
    __shared__ int   ci[NSUB * TOPK];
    __shared__ float fv[TOPK];
    __shared__ int   fi[TOPK];

    if (t < NSUB * TOPK) {
        cv[t] = g_cand_v[(size_t)row * NSUB * TOPK + t];
        ci[t] = g_cand_i[(size_t)row * NSUB * TOPK + t];
    }
    __syncthreads();

    if (t == 0) {
        #pragma unroll
        for (int r = 0; r < TOPK; r++) {
            float gm = cv[0]; int gp = 0;
            #pragma unroll
            for (int j = 1; j < NSUB * TOPK; j++)
                if (cv[j] > gm) { gm = cv[j]; gp = j; }
            fv[r] = gm;
            fi[r] = ci[gp];
            cv[gp] = -FLT_MAX;
        }
    }
    __syncthreads();

    // softmax over 5 (fv sorted desc so fv[0] is the max)
    float mx = fv[0];
    float p0 = __expf(fv[0]-mx), p1 = __expf(fv[1]-mx), p2 = __expf(fv[2]-mx),
          p3 = __expf(fv[3]-mx), p4 = __expf(fv[4]-mx);
    float inv = 1.0f / (p0+p1+p2+p3+p4);
    p0*=inv; p1*=inv; p2*=inv; p3*=inv; p4*=inv;

    const float* e0 = embed_table + (size_t)fi[0]*D;
    const float* e1 = embed_table + (size_t)fi[1]*D;
    const float* e2 = embed_table + (size_t)fi[2]*D;
    const float* e3 = embed_table + (size_t)fi[3]*D;
    const float* e4 = embed_table + (size_t)fi[4]*D;

    float* sce = g_sce + (size_t)row * D;
    #pragma unroll
    for (int j = 0; j < 3; j++) {
        int d = t + j*256;
        sce[d] = p0*e0[d] + p1*e1[d] + p2*e2[d] + p3*e3[d] + p4*e4[d];
    }
}

// ---------------------------------------------------------------------------
// Kernel 2: attention (R9 proven version). Block = (b, 4 queries).
// Grid 128, 256 threads. Warp-per-key scoring, scale folded into staged q.
// ---------------------------------------------------------------------------
__global__ __launch_bounds__(256) void attn_kernel(
    const float* __restrict__ q_in,          // [16,32,768]
    const int*   __restrict__ caption_len)   // [16]
{
    const int b  = blockIdx.x >> 3;
    const int qg = blockIdx.x & 7;           // queries qg*4 .. qg*4+3
    const int t  = threadIdx.x;
    const int wid  = t >> 5;
    const int lane = t & 31;

    const float* sce = g_sce + (size_t)b * CAP * D;
    const float scale = 1.0f / sqrtf((float)D);

    __shared__ float sq[4 * QPAD];
    __shared__ float ssc[4][CAP];

    // stage the 4 query rows with padded stride, pre-scaled
    {
        const float4* qg4 = (const float4*)(q_in + ((size_t)b * AT + qg*4) * D);
        for (int i = t; i < 4 * (D/4); i += 256) {
            int qi = i / (D/4), j = i % (D/4);
            float4 v = qg4[qi * (D/4) + j];
            v.x *= scale; v.y *= scale; v.z *= scale; v.w *= scale;
            *(float4*)&sq[qi * QPAD + j * 4] = v;
        }
    }
    __syncthreads();

    // scores: warp w handles keys w, w+8, ..., w+56
    #pragma unroll
    for (int kb = 0; kb < 8; kb++) {
        const int k = kb * 8 + wid;
        const float4* krow = (const float4*)(sce + (size_t)k * D);
        float a0 = 0.f, a1 = 0.f, a2 = 0.f, a3 = 0.f;
        #pragma unroll
        for (int i = 0; i < 6; i++) {
            const int j = lane + 32 * i;       // float4 index, 0..191
            float4 kk = krow[j];
            float4 q0 = *(const float4*)&sq[0*QPAD + j*4];
            float4 q1 = *(const float4*)&sq[1*QPAD + j*4];
            float4 q2 = *(const float4*)&sq[2*QPAD + j*4];
            float4 q3 = *(const float4*)&sq[3*QPAD + j*4];
            a0 = fmaf(kk.x,q0.x, fmaf(kk.y,q0.y, fmaf(kk.z,q0.z, fmaf(kk.w,q0.w, a0))));
            a1 = fmaf(kk.x,q1.x, fmaf(kk.y,q1.y, fmaf(kk.z,q1.z, fmaf(kk.w,q1.w, a1))));
            a2 = fmaf(kk.x,q2.x, fmaf(kk.y,q2.y, fmaf(kk.z,q2.z, fmaf(kk.w,q2.w, a2))));
            a3 = fmaf(kk.x,q3.x, fmaf(kk.y,q3.y, fmaf(kk.z,q3.z, fmaf(kk.w,q3.w, a3))));
        }
        #pragma unroll
        for (int off = 16; off > 0; off >>= 1) {
            a0 += __shfl_xor_sync(0xffffffffu, a0, off);
            a1 += __shfl_xor_sync(0xffffffffu, a1, off);
            a2 += __shfl_xor_sync(0xffffffffu, a2, off);
            a3 += __shfl_xor_sync(0xffffffffu, a3, off);
        }
        if (lane == 0) {
            ssc[0][k] = a0; ssc[1][k] = a1; ssc[2][k] = a2; ssc[3][k] = a3;
        }
    }
    __syncthreads();

    // softmax per query row; warps 0-3 handle rows 0-3 (scores pre-scaled)
    const int clen = caption_len[b];
    if (wid < 4) {
        float s0 = (lane      < clen) ? ssc[wid][lane]      : -1e9f;
        float s1 = (lane + 32 < clen) ? ssc[wid][lane + 32] : -1e9f;
        float mx = fmaxf(s0, s1);
        #pragma unroll
        for (int off = 16; off > 0; off >>= 1)
            mx = fmaxf(mx, __shfl_xor_sync(0xffffffffu, mx, off));
        float e0 = __expf(s0 - mx), e1 = __expf(s1 - mx);
        float sum = e0 + e1;
        #pragma unroll
        for (int off = 16; off > 0; off >>= 1)
            sum += __shfl_xor_sync(0xffffffffu, sum, off);
        float isum = 1.0f / sum;
        ssc[wid][lane]      = e0 * isum;
        ssc[wid][lane + 32] = e1 * isum;
    }
    __syncthreads();

    // output: thread owns dims t, t+256, t+512 for all 4 queries (coalesced)
    float acc[4][3];
    #pragma unroll
    for (int qi = 0; qi < 4; qi++) { acc[qi][0]=0; acc[qi][1]=0; acc[qi][2]=0; }

    #pragma unroll 2
    for (int k = 0; k < CAP; k++) {
        const float* srow = sce + (size_t)k * D;
        float a0 = srow[t], a1 = srow[t + 256], a2 = srow[t + 512];
        #pragma unroll
        for (int qi = 0; qi < 4; qi++) {
            float aw = ssc[qi][k];
            acc[qi][0] = fmaf(aw, a0, acc[qi][0]);
            acc[qi][1] = fmaf(aw, a1, acc[qi][1]);
            acc[qi][2] = fmaf(aw, a2, acc[qi][2]);
        }
    }
    #pragma unroll
    for (int qi = 0; qi < 4; qi++) {
        float* orow = g_att + ((size_t)b * AT + qg*4 + qi) * D;
        orow[t]       = acc[qi][0];
        orow[t + 256] = acc[qi][1];
        orow[t + 512] = acc[qi][2];
    }
}

// ---------------------------------------------------------------------------
// Kernel 3: final assembly. Block per (b,s). Grid 4096, 192 threads (float4).
// ---------------------------------------------------------------------------
__global__ __launch_bounds__(192) void assemble_kernel(
    const float* __restrict__ embed_table,
    const int*   __restrict__ input_ids,     // [16,256]
    const int*   __restrict__ origin_len,    // [16]
    const int*   __restrict__ target_len,    // [16]
    float*       __restrict__ out)           // [16,256,768]
{
    const int bs = blockIdx.x;
    const int b  = bs >> 8;
    const int s  = bs & 255;
    const int rel = s - origin_len[b];
    const int tl  = target_len[b];

    const float* src;
    if (rel >= 0 && rel < tl)      src = g_att + ((size_t)b * AT + rel) * D;
    else if (rel == tl)            src = embed_table + (size_t)END_ID * D;
    else                           src = embed_table + (size_t)input_ids[bs] * D;

    ((float4*)(out + (size_t)bs * D))[threadIdx.x] = ((const float4*)src)[threadIdx.x];
}

// ---------------------------------------------------------------------------
extern "C" void kernel_launch(void* const* d_in, const int* in_sizes, int n_in,
                              void* d_out, int out_size)
{
    const float* caption_out      = (const float*)d_in[0];   // [16,64,50265]
    const float* embed_table      = (const float*)d_in[1];   // [50265,768]
    const float* inputs_embeds_at = (const float*)d_in[2];   // [16,32,768]
    const int*   input_ids        = (const int*)  d_in[3];   // [16,256]
    const int*   origin_len       = (const int*)  d_in[4];   // [16]
    const int*   target_len       = (const int*)  d_in[5];   // [16]
    const int*   caption_len      = (const int*)  d_in[6];   // [16]
    float* out = (float*)d_out;

    scan_kernel<<<BS * CAP * NSUB, 256>>>(caption_out);
    sce_kernel<<<BS * CAP, 256>>>(embed_table);
    attn_kernel<<<BS * 8, 256>>>(inputs_embeds_at, caption_len);
    assemble_kernel<<<BS * SEQ, 192>>>(embed_table, input_ids,
                                       origin_len, target_len, out);
}